// round 12
// baseline (speedup 1.0000x reference)
#include <cuda_runtime.h>
#include <cuda_bf16.h>
#include <cstdint>

#define Bn    2048
#define CELLn 512
#define Kn    30
#define Ln    1024
#define Vn    80
#define NJ    96
#define KB    8        // K split across blocks in GEMM
#define KCHUNK 64

// partial GEMM sums: g_part[kb][b][j]
__device__ float g_part[KB][Bn][NJ];

// ---------------------------------------------------------------------------
// k1: partial GEMM  g_part[kb][b][j] = sum_{k in 64-chunk kb} x[b][k] * W[j][k]
//     grid 512 = 64 mb-blocks x 8 kb-splits, 256 threads, single smem stage.
//     (round-10 version: scalar FFMA; the f32x2 experiment regressed)
// ---------------------------------------------------------------------------
__global__ __launch_bounds__(256) void k1_gemm(const float* __restrict__ x,
                                               const float* __restrict__ W)
{
    __shared__ float4 sW[96 * 17];
    __shared__ float4 sX[32 * 16];

    const int tid  = threadIdx.x;
    const int lane = tid & 31;
    const int w    = tid >> 5;
    const int mb   = blockIdx.x & 63;
    const int kb   = blockIdx.x >> 6;
    const int b0   = mb * 32;
    const int kc4  = (kb * KCHUNK) >> 2;

    const float4* Wg = (const float4*)W;
    const float4* Xg = (const float4*)x;

    #pragma unroll
    for (int t = 0; t < 6; t++) {
        int i = tid + t * 256;
        int j = i >> 4, c = i & 15;
        if (j < 90) sW[j * 17 + c] = Wg[(size_t)j * (CELLn / 4) + kc4 + c];
    }
    #pragma unroll
    for (int t = 0; t < 2; t++) {
        int i = tid + t * 256;
        int bl = i >> 4, c = i & 15;
        sX[bl * 16 + c] = Xg[(size_t)(b0 + bl) * (CELLn / 4) + kc4 + c];
    }
    __syncthreads();

    float acc[4][3] = {};
    #pragma unroll
    for (int kc = 0; kc < 16; kc++) {
        float4 w0 = sW[(3 * lane + 0) * 17 + kc];
        float4 w1 = sW[(3 * lane + 1) * 17 + kc];
        float4 w2 = sW[(3 * lane + 2) * 17 + kc];
        #pragma unroll
        for (int u = 0; u < 4; u++) {
            float4 xv = sX[(w * 4 + u) * 16 + kc];
            acc[u][0] += xv.x * w0.x + xv.y * w0.y + xv.z * w0.z + xv.w * w0.w;
            acc[u][1] += xv.x * w1.x + xv.y * w1.y + xv.z * w1.z + xv.w * w1.w;
            acc[u][2] += xv.x * w2.x + xv.y * w2.y + xv.z * w2.z + xv.w * w2.w;
        }
    }

    #pragma unroll
    for (int u = 0; u < 4; u++) {
        const int b = b0 + w * 4 + u;
        #pragma unroll
        for (int c = 0; c < 3; c++)
            g_part[kb][b][3 * lane + c] = acc[u][c];
    }
}

// ---------------------------------------------------------------------------
// k2: ONE WARP per b, zero block barriers. 4 warps (128 thr) per block,
//     512 blocks -> all 2048 warps resident simultaneously (~14/SM).
//     Per warp:  zero-fill phi row (STG.128, fire-and-forget)
//             -> params finish (24 L2 loads, exp, window)  [__syncwarp]
//             -> windowed phi (l <= lend)                  [__syncwarp]
//             -> contraction: lanes 0..19 own v-columns, MLP=8 gmem stream
//             -> one STG.128 per lane. No cross-warp anything.
// ---------------------------------------------------------------------------
__global__ __launch_bounds__(128) void k2_fused(
    const float* __restrict__ onehots, const float* __restrict__ kappa_old,
    const float* __restrict__ text_lens, const float* __restrict__ bias,
    float* __restrict__ out)
{
    __shared__ float  s_phi[4][Ln];      // 16 KB (per-warp slice)
    __shared__ float4 s_abk[4][30];      // alpha, beta, kappa per warp

    const int lane = threadIdx.x & 31;
    const int wid  = threadIdx.x >> 5;
    const int b    = blockIdx.x * 4 + wid;

    const float4* M4 = (const float4*)onehots + (size_t)b * (Ln * Vn / 4);
    float* phi_out = out + (size_t)Bn * Vn + (size_t)Bn * Kn + (size_t)b * (Ln + 1);

    // ---- zero-fill phi row (vectorized; overlaps the params loads below) ----
    {
        const int l0  = (4 - (b & 3)) & 3;          // first 16B-aligned l
        const int n4  = (Ln + 1 - l0) >> 2;
        const int tail = Ln + 1 - l0 - (n4 << 2);
        if (lane < l0) phi_out[lane] = 0.0f;
        float4* p4 = (float4*)(phi_out + l0);
        const float4 z4 = make_float4(0.f, 0.f, 0.f, 0.f);
        for (int i = lane; i < n4; i += 32) p4[i] = z4;
        if (lane < tail) phi_out[l0 + (n4 << 2) + lane] = 0.0f;
    }

    // ---- params finish + window ----
    float wend = 0.0f;
    if (lane < 30) {
        float sa = 0.f, sb = 0.f, sk = 0.f;
        #pragma unroll
        for (int kb = 0; kb < KB; kb++) {
            sa += g_part[kb][b][lane];
            sb += g_part[kb][b][30 + lane];
            sk += g_part[kb][b][60 + lane];
        }
        const float alpha = __expf(sa + bias[lane]);
        const float beta  = __expf(sb + bias[30 + lane]);
        const float kap   = kappa_old[b * Kn + lane] + __expf(sk + bias[60 + lane]);
        out[(size_t)Bn * Vn + (size_t)b * Kn + lane] = kap;
        s_abk[wid][lane] = make_float4(alpha, beta, kap, 0.f);
        wend = kap + sqrtf(110.0f / beta);
    }
    #pragma unroll
    for (int o = 16; o; o >>= 1)
        wend = fmaxf(wend, __shfl_xor_sync(0xffffffffu, wend, o));
    const int lend = min((int)ceilf(wend), Ln);
    __syncwarp();   // s_abk visible; zero-fill ordered before phi overwrites

    const float scale = (float)Ln / text_lens[b];

    // ---- windowed phi (l <= lend only; zeros beyond already written) ----
    for (int l = lane; l <= lend; l += 32) {
        const float lf = (float)l;
        float s = 0.0f;
        #pragma unroll 6
        for (int k = 0; k < Kn; k++) {
            float4 p = s_abk[wid][k];
            float d = p.z - lf;
            float gv = -p.y * d * d;
            if (gv > -110.0f) s += p.x * __expf(gv);
        }
        const float v = s * scale;
        phi_out[l] = v;
        if (l < Ln) s_phi[wid][l] = v;
    }
    __syncwarp();   // s_phi visible to all lanes of this warp

    // ---- contraction: this warp owns ALL rows; lanes 0..19 own v-columns ----
    const int rows = min(lend + 1, Ln);
    if (lane < 20) {
        float4 acc = make_float4(0.f, 0.f, 0.f, 0.f);
        const float4* Mp = M4 + lane;
        int r = 0;
        // MLP=8
        for (; r + 7 < rows; r += 8, Mp += 160) {
            float4 m0 = __ldcs(Mp);
            float4 m1 = __ldcs(Mp + 20);
            float4 m2 = __ldcs(Mp + 40);
            float4 m3 = __ldcs(Mp + 60);
            float4 m4 = __ldcs(Mp + 80);
            float4 m5 = __ldcs(Mp + 100);
            float4 m6 = __ldcs(Mp + 120);
            float4 m7 = __ldcs(Mp + 140);
            float p0 = s_phi[wid][r];
            float p1 = s_phi[wid][r + 1];
            float p2 = s_phi[wid][r + 2];
            float p3 = s_phi[wid][r + 3];
            float p4 = s_phi[wid][r + 4];
            float p5 = s_phi[wid][r + 5];
            float p6 = s_phi[wid][r + 6];
            float p7 = s_phi[wid][r + 7];
            acc.x += p0 * m0.x; acc.y += p0 * m0.y; acc.z += p0 * m0.z; acc.w += p0 * m0.w;
            acc.x += p1 * m1.x; acc.y += p1 * m1.y; acc.z += p1 * m1.z; acc.w += p1 * m1.w;
            acc.x += p2 * m2.x; acc.y += p2 * m2.y; acc.z += p2 * m2.z; acc.w += p2 * m2.w;
            acc.x += p3 * m3.x; acc.y += p3 * m3.y; acc.z += p3 * m3.z; acc.w += p3 * m3.w;
            acc.x += p4 * m4.x; acc.y += p4 * m4.y; acc.z += p4 * m4.z; acc.w += p4 * m4.w;
            acc.x += p5 * m5.x; acc.y += p5 * m5.y; acc.z += p5 * m5.z; acc.w += p5 * m5.w;
            acc.x += p6 * m6.x; acc.y += p6 * m6.y; acc.z += p6 * m6.z; acc.w += p6 * m6.w;
            acc.x += p7 * m7.x; acc.y += p7 * m7.y; acc.z += p7 * m7.z; acc.w += p7 * m7.w;
        }
        for (; r < rows; r++, Mp += 20) {
            float4 m = __ldcs(Mp);
            float p = s_phi[wid][r];
            acc.x += p * m.x; acc.y += p * m.y; acc.z += p * m.z; acc.w += p * m.w;
        }
        ((float4*)(out + (size_t)b * Vn))[lane] = acc;
    }
}

// ---------------------------------------------------------------------------
extern "C" void kernel_launch(void* const* d_in, const int* in_sizes, int n_in,
                              void* d_out, int out_size)
{
    const float* x         = (const float*)d_in[0];
    const float* kappa_old = (const float*)d_in[1];
    const float* onehots   = (const float*)d_in[2];
    const float* text_lens = (const float*)d_in[3];
    const float* W         = (const float*)d_in[4];
    const float* bias      = (const float*)d_in[5];
    float* out = (float*)d_out;

    k1_gemm<<<512, 256>>>(x, W);
    k2_fused<<<Bn / 4, 128>>>(onehots, kappa_old, text_lens, bias, out);
}

// round 13
// speedup vs baseline: 1.0128x; 1.0128x over previous
#include <cuda_runtime.h>
#include <cuda_bf16.h>
#include <cstdint>

#define Bn    2048
#define CELLn 512
#define Kn    30
#define Ln    1024
#define Vn    80
#define NJ    96
#define KB    8        // K split across blocks in GEMM
#define KCHUNK 64
#define CH    128      // k2b rows per chunk

// partial GEMM sums: g_part[kb][b][j]
__device__ float g_part[KB][Bn][NJ];
__device__ int   g_rows[Bn];

// ---------------------------------------------------------------------------
// k1: partial GEMM  g_part[kb][b][j] = sum_{k in 64-chunk kb} x[b][k] * W[j][k]
//     grid 512 = 64 mb-blocks x 8 kb-splits, 256 threads, single smem stage.
// ---------------------------------------------------------------------------
__global__ __launch_bounds__(256) void k1_gemm(const float* __restrict__ x,
                                               const float* __restrict__ W)
{
    __shared__ float4 sW[96 * 17];
    __shared__ float4 sX[32 * 16];

    const int tid  = threadIdx.x;
    const int lane = tid & 31;
    const int w    = tid >> 5;
    const int mb   = blockIdx.x & 63;
    const int kb   = blockIdx.x >> 6;
    const int b0   = mb * 32;
    const int kc4  = (kb * KCHUNK) >> 2;

    const float4* Wg = (const float4*)W;
    const float4* Xg = (const float4*)x;

    #pragma unroll
    for (int t = 0; t < 6; t++) {
        int i = tid + t * 256;
        int j = i >> 4, c = i & 15;
        if (j < 90) sW[j * 17 + c] = Wg[(size_t)j * (CELLn / 4) + kc4 + c];
    }
    #pragma unroll
    for (int t = 0; t < 2; t++) {
        int i = tid + t * 256;
        int bl = i >> 4, c = i & 15;
        sX[bl * 16 + c] = Xg[(size_t)(b0 + bl) * (CELLn / 4) + kc4 + c];
    }
    __syncthreads();

    float acc[4][3] = {};
    #pragma unroll
    for (int kc = 0; kc < 16; kc++) {
        float4 w0 = sW[(3 * lane + 0) * 17 + kc];
        float4 w1 = sW[(3 * lane + 1) * 17 + kc];
        float4 w2 = sW[(3 * lane + 2) * 17 + kc];
        #pragma unroll
        for (int u = 0; u < 4; u++) {
            float4 xv = sX[(w * 4 + u) * 16 + kc];
            acc[u][0] += xv.x * w0.x + xv.y * w0.y + xv.z * w0.z + xv.w * w0.w;
            acc[u][1] += xv.x * w1.x + xv.y * w1.y + xv.z * w1.z + xv.w * w1.w;
            acc[u][2] += xv.x * w2.x + xv.y * w2.y + xv.z * w2.z + xv.w * w2.w;
        }
    }

    #pragma unroll
    for (int u = 0; u < 4; u++) {
        const int b = b0 + w * 4 + u;
        #pragma unroll
        for (int c = 0; c < 3; c++)
            g_part[kb][b][3 * lane + c] = acc[u][c];
    }
}

// ---------------------------------------------------------------------------
// k2a: params finish + kappa + window + windowed phi + phi zero-fill.
//      Also zeroes the w output region (k2b accumulates with atomics).
//      Warp per b; 256 blocks x 256 threads. Short chain, no block barriers.
// ---------------------------------------------------------------------------
__global__ __launch_bounds__(256) void k2a_phi(
    const float* __restrict__ kappa_old, const float* __restrict__ text_lens,
    const float* __restrict__ bias, float* __restrict__ out)
{
    __shared__ float4 s_abk[8][30];

    const int tid  = threadIdx.x;
    const int lane = tid & 31;
    const int wid  = tid >> 5;
    const int b    = blockIdx.x * 8 + wid;

    // zero the w region (2048*80 floats = 40960 float4 over 65536 threads)
    {
        const int gtid = blockIdx.x * 256 + tid;
        if (gtid < Bn * Vn / 4)
            ((float4*)out)[gtid] = make_float4(0.f, 0.f, 0.f, 0.f);
    }

    float* phi_out = out + (size_t)Bn * Vn + (size_t)Bn * Kn + (size_t)b * (Ln + 1);

    // phi row zero-fill (vectorized, fire-and-forget)
    {
        const int l0  = (4 - (b & 3)) & 3;
        const int n4  = (Ln + 1 - l0) >> 2;
        const int tail = Ln + 1 - l0 - (n4 << 2);
        if (lane < l0) phi_out[lane] = 0.0f;
        float4* p4 = (float4*)(phi_out + l0);
        const float4 z4 = make_float4(0.f, 0.f, 0.f, 0.f);
        for (int i = lane; i < n4; i += 32) p4[i] = z4;
        if (lane < tail) phi_out[l0 + (n4 << 2) + lane] = 0.0f;
    }

    // params finish + window
    float wend = 0.0f;
    if (lane < 30) {
        float sa = 0.f, sb = 0.f, sk = 0.f;
        #pragma unroll
        for (int kb = 0; kb < KB; kb++) {
            sa += g_part[kb][b][lane];
            sb += g_part[kb][b][30 + lane];
            sk += g_part[kb][b][60 + lane];
        }
        const float alpha = __expf(sa + bias[lane]);
        const float beta  = __expf(sb + bias[30 + lane]);
        const float kap   = kappa_old[b * Kn + lane] + __expf(sk + bias[60 + lane]);
        out[(size_t)Bn * Vn + (size_t)b * Kn + lane] = kap;
        s_abk[wid][lane] = make_float4(alpha, beta, kap, 0.f);
        wend = kap + sqrtf(110.0f / beta);
    }
    #pragma unroll
    for (int o = 16; o; o >>= 1)
        wend = fmaxf(wend, __shfl_xor_sync(0xffffffffu, wend, o));
    const int lend = min((int)ceilf(wend), Ln);
    if (lane == 0) g_rows[b] = min(lend + 1, Ln);
    __syncwarp();   // s_abk visible; zero-fill ordered before windowed writes

    const float scale = (float)Ln / text_lens[b];

    // windowed phi (zeros beyond lend already written)
    for (int l = lane; l <= lend; l += 32) {
        const float lf = (float)l;
        float s = 0.0f;
        #pragma unroll 6
        for (int k = 0; k < Kn; k++) {
            float4 p = s_abk[wid][k];
            float d = p.z - lf;
            float gv = -p.y * d * d;
            if (gv > -110.0f) s += p.x * __expf(gv);
        }
        phi_out[l] = s * scale;
    }
}

// ---------------------------------------------------------------------------
// k2b: pure contraction. Grid 4096 = 2048 b's x 2 chunks; 128 threads.
//      chunk 0: rows [0,128); chunk 1: rows [128, rows)  (freak-case loop).
//      Load phi chunk to smem, 4-warp MLP-8 stream over onehots window,
//      smem reduce, 80 atomicAdds into w (zeroed by k2a).
// ---------------------------------------------------------------------------
__global__ __launch_bounds__(128, 12) void k2b_w(
    const float* __restrict__ onehots, const float* __restrict__ out_ro,
    float* __restrict__ out)
{
    __shared__ float  s_phi[Ln - CH];     // max chunk span = 896 floats
    __shared__ float4 s_red[4][20];

    const int tid  = threadIdx.x;
    const int lane = tid & 31;
    const int wg   = tid >> 5;
    const int b    = blockIdx.x & (Bn - 1);
    const int c    = blockIdx.x >> 11;

    const int rows = g_rows[b];
    const int r0   = c * CH;

    const float* phi = out_ro + (size_t)Bn * Vn + (size_t)Bn * Kn + (size_t)b * (Ln + 1);
    // issue first-128 phi loads immediately (always in-bounds: r0+127 <= 255 < 1025)
    const float ph0 = phi[r0 + tid];

    if (r0 >= rows) return;
    const int r1 = (c == 0) ? min(rows, CH) : rows;

    s_phi[tid] = ph0;
    for (int i = CH + tid; i < r1 - r0; i += 128) s_phi[i] = phi[r0 + i];
    __syncthreads();

    const float4* M4 = (const float4*)onehots + (size_t)b * (Ln * Vn / 4);

    if (lane < 20) {
        float4 acc = make_float4(0.f, 0.f, 0.f, 0.f);
        int r = r0 + wg;
        const float4* Mp = M4 + (size_t)r * 20 + lane;
        // MLP=8 (rows r, r+4, ..., r+28)
        for (; r + 28 < r1; r += 32, Mp += 640) {
            float4 m0 = __ldcs(Mp);
            float4 m1 = __ldcs(Mp + 80);
            float4 m2 = __ldcs(Mp + 160);
            float4 m3 = __ldcs(Mp + 240);
            float4 m4 = __ldcs(Mp + 320);
            float4 m5 = __ldcs(Mp + 400);
            float4 m6 = __ldcs(Mp + 480);
            float4 m7 = __ldcs(Mp + 560);
            float p0 = s_phi[r - r0];
            float p1 = s_phi[r - r0 + 4];
            float p2 = s_phi[r - r0 + 8];
            float p3 = s_phi[r - r0 + 12];
            float p4 = s_phi[r - r0 + 16];
            float p5 = s_phi[r - r0 + 20];
            float p6 = s_phi[r - r0 + 24];
            float p7 = s_phi[r - r0 + 28];
            acc.x += p0 * m0.x; acc.y += p0 * m0.y; acc.z += p0 * m0.z; acc.w += p0 * m0.w;
            acc.x += p1 * m1.x; acc.y += p1 * m1.y; acc.z += p1 * m1.z; acc.w += p1 * m1.w;
            acc.x += p2 * m2.x; acc.y += p2 * m2.y; acc.z += p2 * m2.z; acc.w += p2 * m2.w;
            acc.x += p3 * m3.x; acc.y += p3 * m3.y; acc.z += p3 * m3.z; acc.w += p3 * m3.w;
            acc.x += p4 * m4.x; acc.y += p4 * m4.y; acc.z += p4 * m4.z; acc.w += p4 * m4.w;
            acc.x += p5 * m5.x; acc.y += p5 * m5.y; acc.z += p5 * m5.z; acc.w += p5 * m5.w;
            acc.x += p6 * m6.x; acc.y += p6 * m6.y; acc.z += p6 * m6.z; acc.w += p6 * m6.w;
            acc.x += p7 * m7.x; acc.y += p7 * m7.y; acc.z += p7 * m7.z; acc.w += p7 * m7.w;
        }
        for (; r < r1; r += 4, Mp += 80) {
            float4 m = __ldcs(Mp);
            float p = s_phi[r - r0];
            acc.x += p * m.x; acc.y += p * m.y; acc.z += p * m.z; acc.w += p * m.w;
        }
        s_red[wg][lane] = acc;
    }
    __syncthreads();

    if (wg == 0 && lane < 20) {
        float4 a0 = s_red[0][lane];
        float4 a1 = s_red[1][lane];
        float4 a2 = s_red[2][lane];
        float4 a3 = s_red[3][lane];
        float* wp = out + (size_t)b * Vn + 4 * lane;
        atomicAdd(wp + 0, (a0.x + a1.x) + (a2.x + a3.x));
        atomicAdd(wp + 1, (a0.y + a1.y) + (a2.y + a3.y));
        atomicAdd(wp + 2, (a0.z + a1.z) + (a2.z + a3.z));
        atomicAdd(wp + 3, (a0.w + a1.w) + (a2.w + a3.w));
    }
}

// ---------------------------------------------------------------------------
extern "C" void kernel_launch(void* const* d_in, const int* in_sizes, int n_in,
                              void* d_out, int out_size)
{
    const float* x         = (const float*)d_in[0];
    const float* kappa_old = (const float*)d_in[1];
    const float* onehots   = (const float*)d_in[2];
    const float* text_lens = (const float*)d_in[3];
    const float* W         = (const float*)d_in[4];
    const float* bias      = (const float*)d_in[5];
    float* out = (float*)d_out;

    k1_gemm<<<512, 256>>>(x, W);
    k2a_phi<<<Bn / 8, 256>>>(kappa_old, text_lens, bias, out);
    k2b_w<<<Bn * 2, 128>>>(onehots, out, out);
}